// round 13
// baseline (speedup 1.0000x reference)
#include <cuda_runtime.h>
#include <cstdint>

// ---- problem constants ----
#define BATCH   1024
#define NNODES  100
#define KD      640      // key dim (5*128)
#define KD4     160      // key dim in float4
#define POOL    128
#define TOPK    4
#define PD      2304     // prompt dim
#define PD4     576
#define SEGB    9216u    // bytes per (row,k) prompt segment = PD*4

// ---- output layout (flat float32, reference return order) ----
#define OUT_RS  (BATCH*TOPK*PD)          // 9437184
#define OUT_SIM (OUT_RS + 1)             // 9437185
#define OUT_US  (OUT_SIM + BATCH*POOL)   // 9568257

// ---- device scratch ----
__device__ float g_xnorm[BATCH * KD];
__device__ float g_keynorm[POOL * KD];
__device__ int   g_idx[BATCH * TOPK];
__device__ float g_partial[128];
__device__ int   g_scnt;    // sim blocks done (==128); reset by final block

// ---- f32x2 packed-FMA helpers (sm_103a) ----
__device__ __forceinline__ void fma2(unsigned long long& acc,
                                     unsigned long long a,
                                     unsigned long long b) {
    asm("fma.rn.f32x2 %0, %1, %2, %0;" : "+l"(acc) : "l"(a), "l"(b));
}
__device__ __forceinline__ float unpack_sum(unsigned long long v) {
    float lo, hi;
    asm("mov.b64 {%0, %1}, %2;" : "=f"(lo), "=f"(hi) : "l"(v));
    return lo + hi;
}
__device__ __forceinline__ void waitge(volatile int* p, int tgt) {
    while (*p < tgt) __nanosleep(64);
}
__device__ __forceinline__ uint32_t smem_u32(const void* p) {
    uint32_t a;
    asm("{ .reg .u64 t; cvta.to.shared.u64 t, %1; cvt.u32.u64 %0, t; }"
        : "=r"(a) : "l"(p));
    return a;
}

// ============================================================
// Kernel 1: blocks 0..1023 -> per-row mean + L2 normalize
//           blocks 1024..1151 -> pool-key normalize
// (proven 80%-DRAM geometry; normalizing the SUM == normalizing
//  the mean by scale invariance)
// ============================================================
__global__ __launch_bounds__(320, 4) void k1_norm(const float4* __restrict__ x,
                                                  const float4* __restrict__ pk) {
    const int c   = threadIdx.x;                        // 0..159
    const int tid = threadIdx.y * 160 + threadIdx.x;    // 0..319
    const int lane = tid & 31, warp = tid >> 5;

    __shared__ float4 part[160];
    __shared__ float  wss[10];

    if (blockIdx.x < BATCH) {
        const int row = blockIdx.x;
        const float4* xp = x + (size_t)row * (NNODES * KD4)
                             + (size_t)threadIdx.y * 50 * KD4 + c;
        float4 a = make_float4(0.f, 0.f, 0.f, 0.f);
        #pragma unroll 10
        for (int n = 0; n < 50; n++) {
            float4 v = xp[(size_t)n * KD4];
            a.x += v.x; a.y += v.y; a.z += v.z; a.w += v.w;
        }
        if (threadIdx.y == 1) part[c] = a;
        __syncthreads();
        float ss = 0.f;
        if (threadIdx.y == 0) {
            float4 b = part[c];
            a.x += b.x; a.y += b.y; a.z += b.z; a.w += b.w;
            ss = a.x*a.x + a.y*a.y + a.z*a.z + a.w*a.w;
        }
        #pragma unroll
        for (int o = 16; o; o >>= 1) ss += __shfl_xor_sync(0xffffffffu, ss, o);
        if (lane == 0) wss[warp] = ss;
        __syncthreads();
        if (threadIdx.y == 0) {
            float tot = wss[0] + wss[1] + wss[2] + wss[3] + wss[4];
            tot = fmaxf(tot, 1e-12f);
            float rs = rsqrtf(tot);
            rs = rs * (1.5f - 0.5f * tot * rs * rs);   // NR refine
            float4* o4 = reinterpret_cast<float4*>(g_xnorm);
            o4[(size_t)row * KD4 + c] = make_float4(a.x*rs, a.y*rs, a.z*rs, a.w*rs);
        }
    } else {
        const int p = blockIdx.x - BATCH;
        float4 v = make_float4(0.f, 0.f, 0.f, 0.f);
        float ss = 0.f;
        if (tid < 160) {
            v = pk[(size_t)p * KD4 + tid];
            ss = v.x*v.x + v.y*v.y + v.z*v.z + v.w*v.w;
        }
        #pragma unroll
        for (int o = 16; o; o >>= 1) ss += __shfl_xor_sync(0xffffffffu, ss, o);
        if (lane == 0) wss[warp] = ss;
        __syncthreads();
        float tot = wss[0] + wss[1] + wss[2] + wss[3] + wss[4];
        tot = fmaxf(tot, 1e-12f);
        float rs = rsqrtf(tot);
        rs = rs * (1.5f - 0.5f * tot * rs * rs);
        if (tid < 160) {
            float4* o4 = reinterpret_cast<float4*>(g_keynorm);
            o4[(size_t)p * KD4 + tid] = make_float4(v.x*rs, v.y*rs, v.z*rs, v.w*rs);
        }
    }
}

// ============================================================
// Kernel M2: blocks 0..127 -> sim GEMM (8 rows x 128 pools) + top-4
// + sim write + BULK-ASYNC gather of the 32 selected prompt segments
// (cp.async.bulk DMA through reused smem; zero per-thread load/store
// instructions). Block 128 -> final reduce + usage (+ counter reset).
// ============================================================
__global__ __launch_bounds__(512)
void kM2(const float4* __restrict__ prompt, float* __restrict__ out) {
    const int bid = blockIdx.x;
    const int t   = threadIdx.x;
    const int w   = t >> 5, lane = t & 31;

    if (bid < POOL) {
        // sbuf doubles as: xs[8][644] (20.6KB) during GEMM,
        // then 4-segment DMA staging buffer (36.8KB) during gather.
        __shared__ __align__(16) unsigned char sbuf[4 * SEGB];
        __shared__ float sims[8][132];
        __shared__ float wsum[8];
        __shared__ int   sidx[32];
        __shared__ __align__(8) unsigned long long gmbar;

        float (*xs)[644] = reinterpret_cast<float (*)[644]>(sbuf);

        const int rb = bid * 8;
        const int pg = t >> 4;             // 0..31 -> pools pg*4..+3
        const int ds = t & 15;             // dim slot

        if (t == 0) {
            uint32_t mb = smem_u32(&gmbar);
            asm volatile("mbarrier.init.shared.b64 [%0], 1;" :: "r"(mb) : "memory");
        }

        // stage 8 x rows (coalesced)
        {
            const float4* xg = reinterpret_cast<const float4*>(g_xnorm);
            #pragma unroll
            for (int i = 0; i < 3; i++) {
                int l = t + 512 * i;                // covers 1280
                if (l < 1280) {
                    int r = l / 160, col = l - r * 160;
                    *reinterpret_cast<float4*>(&xs[r][col * 4]) =
                        xg[(size_t)(rb + r) * KD4 + col];
                }
            }
        }
        __syncthreads();

        const ulonglong2* kg = reinterpret_cast<const ulonglong2*>(g_keynorm);

        unsigned long long acc[4][8];      // [pool u][row r]
        #pragma unroll
        for (int u = 0; u < 4; u++)
            #pragma unroll
            for (int r = 0; r < 8; r++) acc[u][r] = 0ull;

        #pragma unroll
        for (int c = 0; c < 10; c++) {
            ulonglong2 kv[4];
            #pragma unroll
            for (int u = 0; u < 4; u++)
                kv[u] = kg[(size_t)(pg * 4 + u) * KD4 + c * 16 + ds];
            #pragma unroll
            for (int r = 0; r < 8; r++) {
                ulonglong2 xv = *reinterpret_cast<const ulonglong2*>(
                    &xs[r][c * 64 + ds * 4]);
                #pragma unroll
                for (int u = 0; u < 4; u++) {
                    fma2(acc[u][r], xv.x, kv[u].x);
                    fma2(acc[u][r], xv.y, kv[u].y);
                }
            }
        }

        #pragma unroll
        for (int u = 0; u < 4; u++) {
            #pragma unroll
            for (int r = 0; r < 8; r++) {
                float v = unpack_sum(acc[u][r]);
                #pragma unroll
                for (int o = 8; o; o >>= 1) v += __shfl_xor_sync(0xffffffffu, v, o);
                if (ds == 0) sims[r][pg * 4 + u] = v;
            }
        }
        __syncthreads();   // sims ready; xs now dead -> sbuf reusable

        // similarity output (coalesced)
        for (int l = t; l < 8 * POOL; l += 512) {
            int rr = l >> 7, pp = l & 127;
            out[OUT_SIM + (size_t)(rb + rr) * POOL + pp] = sims[rr][pp];
        }

        // top-4: warps 0..7 -> rows 0..7 (monotone-bits composite key,
        // smallest index on ties -> matches jax.lax.top_k)
        if (w < 8) {
            float vals[4];
            #pragma unroll
            for (int s = 0; s < 4; s++) vals[s] = sims[w][lane + 32*s];
            float vsum = 0.f;
            #pragma unroll
            for (int k = 0; k < TOPK; k++) {
                unsigned long long best = 0ull;
                #pragma unroll
                for (int s = 0; s < 4; s++) {
                    unsigned u = __float_as_uint(vals[s]);
                    u = (u & 0x80000000u) ? ~u : (u | 0x80000000u);
                    unsigned long long comp =
                        ((unsigned long long)u << 32) | (127u - (lane + 32u*s));
                    if (comp > best) best = comp;
                }
                #pragma unroll
                for (int o = 16; o; o >>= 1) {
                    unsigned long long other = __shfl_xor_sync(0xffffffffu, best, o);
                    if (other > best) best = other;
                }
                unsigned pool = 127u - (unsigned)(best & 0xffffffffu);
                unsigned ub = (unsigned)(best >> 32);
                unsigned orig = (ub & 0x80000000u) ? (ub ^ 0x80000000u) : ~ub;
                vsum += __uint_as_float(orig);
                if (lane == (int)(pool & 31u)) vals[pool >> 5] = -1e30f;
                if (lane == 0) {
                    g_idx[(rb + w) * TOPK + k] = (int)pool;
                    sidx[w * 4 + k] = (int)pool;
                }
            }
            if (lane == 0) wsum[w] = vsum;
        }
        __syncthreads();

        if (t == 0) {
            float s = 0.f;
            #pragma unroll
            for (int j = 0; j < 8; j++) s += wsum[j];   // fixed order
            g_partial[bid] = s;
            __threadfence();             // publish g_idx/g_partial
            atomicAdd(&g_scnt, 1);
        }

        // ---- bulk-async gather: 32 segments of 9216B via DMA,
        //      8 rounds x 4 segments staged through sbuf ----
        if (t == 0) {
            const uint32_t mb = smem_u32(&gmbar);
            const uint32_t sb = smem_u32(sbuf);
            const char* psrc = reinterpret_cast<const char*>(prompt);
            char* pdst = reinterpret_cast<char*>(out) + (size_t)rb * 4 * SEGB;
            int phase = 0;
            #pragma unroll 1
            for (int rd = 0; rd < 8; rd++) {
                asm volatile(
                    "mbarrier.arrive.expect_tx.shared.b64 _, [%0], %1;"
                    :: "r"(mb), "r"(4u * SEGB) : "memory");
                #pragma unroll
                for (int s = 0; s < 4; s++) {
                    const char* src = psrc + (size_t)sidx[rd * 4 + s] * SEGB;
                    asm volatile(
                        "cp.async.bulk.shared::cluster.global.mbarrier::complete_tx::bytes "
                        "[%0], [%1], %2, [%3];"
                        :: "r"(sb + s * SEGB), "l"(src), "r"(SEGB), "r"(mb)
                        : "memory");
                }
                // wait for this round's 36864 bytes
                asm volatile(
                    "{\n\t.reg .pred p;\n\t"
                    "WAITL_%=:\n\t"
                    "mbarrier.try_wait.parity.shared.b64 p, [%0], %1;\n\t"
                    "@!p bra WAITL_%=;\n\t}"
                    :: "r"(mb), "r"((unsigned)phase) : "memory");
                phase ^= 1;
                #pragma unroll
                for (int s = 0; s < 4; s++) {
                    asm volatile(
                        "cp.async.bulk.global.shared::cta.bulk_group [%0], [%1], %2;"
                        :: "l"(pdst + (size_t)(rd * 4 + s) * SEGB),
                           "r"(sb + s * SEGB), "r"(SEGB)
                        : "memory");
                }
                asm volatile("cp.async.bulk.commit_group;" ::: "memory");
                asm volatile("cp.async.bulk.wait_group 0;" ::: "memory");
            }
        }
        __syncthreads();

    } else {
        // ---------------- final: reduce_sim + usage + reset ----------------
        __shared__ float red[128];
        __shared__ int   histo[128];
        if (t == 0) { waitge(&g_scnt, 128); __threadfence(); }
        __syncthreads();
        if (t < 128) { red[t] = g_partial[t]; histo[t] = 0; }
        __syncthreads();
        #pragma unroll
        for (int o = 64; o; o >>= 1) {
            if (t < o) red[t] += red[t + o];
            __syncthreads();
        }
        if (t == 0) out[OUT_RS] = red[0] * (1.0f / (float)BATCH);
        #pragma unroll
        for (int j = 0; j < 8; j++)
            atomicAdd(&histo[g_idx[t * 8 + j]], 1);
        __syncthreads();
        if (t < 128) out[OUT_US + t] = (float)histo[t];
        if (t == 0) g_scnt = 0;   // reset for next graph replay
    }
}

// ============================================================
extern "C" void kernel_launch(void* const* d_in, const int* in_sizes, int n_in,
                              void* d_out, int out_size) {
    const float* x      = (const float*)d_in[0];  // [1024, 100, 640]
    const float* prompt = (const float*)d_in[1];  // [128, 1, 2304]
    const float* pkey   = (const float*)d_in[2];  // [128, 640]
    float* out = (float*)d_out;

    k1_norm<<<BATCH + POOL, dim3(160, 2)>>>(
        reinterpret_cast<const float4*>(x),
        reinterpret_cast<const float4*>(pkey));
    kM2<<<POOL + 1, 512>>>(reinterpret_cast<const float4*>(prompt), out);
}

// round 14
// speedup vs baseline: 1.0615x; 1.0615x over previous
#include <cuda_runtime.h>
#include <cstdint>

// ---- problem constants ----
#define BATCH   1024
#define NNODES  100
#define KD      640      // key dim (5*128)
#define KD4     160      // key dim in float4
#define POOL    128
#define TOPK    4
#define PD      2304     // prompt dim
#define PD4     576

// ---- output layout (flat float32, reference return order) ----
#define OUT_RS  (BATCH*TOPK*PD)          // 9437184
#define OUT_SIM (OUT_RS + 1)             // 9437185
#define OUT_US  (OUT_SIM + BATCH*POOL)   // 9568257

// ---- device scratch ----
__device__ float g_xnorm[BATCH * KD];
__device__ float g_keynorm[POOL * KD];
__device__ int   g_idx[BATCH * TOPK];
__device__ float g_partial[128];
__device__ int   g_scnt;    // sim blocks done (==128); reset by final block

// ---- f32x2 packed-FMA helpers (sm_103a) ----
__device__ __forceinline__ void fma2(unsigned long long& acc,
                                     unsigned long long a,
                                     unsigned long long b) {
    asm("fma.rn.f32x2 %0, %1, %2, %0;" : "+l"(acc) : "l"(a), "l"(b));
}
__device__ __forceinline__ float unpack_sum(unsigned long long v) {
    float lo, hi;
    asm("mov.b64 {%0, %1}, %2;" : "=f"(lo), "=f"(hi) : "l"(v));
    return lo + hi;
}
__device__ __forceinline__ void waitge(volatile int* p, int tgt) {
    while (*p < tgt) __nanosleep(64);
}

// ============================================================
// Kernel 1: blocks 0..1023 -> per-row mean + L2 normalize
//           blocks 1024..1151 -> pool-key normalize
// (proven 80%-DRAM geometry; normalizing the SUM == normalizing
//  the mean by scale invariance)
// ============================================================
__global__ __launch_bounds__(320, 4) void k1_norm(const float4* __restrict__ x,
                                                  const float4* __restrict__ pk) {
    const int c   = threadIdx.x;                        // 0..159
    const int tid = threadIdx.y * 160 + threadIdx.x;    // 0..319
    const int lane = tid & 31, warp = tid >> 5;

    __shared__ float4 part[160];
    __shared__ float  wss[10];

    if (blockIdx.x < BATCH) {
        const int row = blockIdx.x;
        const float4* xp = x + (size_t)row * (NNODES * KD4)
                             + (size_t)threadIdx.y * 50 * KD4 + c;
        float4 a = make_float4(0.f, 0.f, 0.f, 0.f);
        #pragma unroll 10
        for (int n = 0; n < 50; n++) {
            float4 v = xp[(size_t)n * KD4];
            a.x += v.x; a.y += v.y; a.z += v.z; a.w += v.w;
        }
        if (threadIdx.y == 1) part[c] = a;
        __syncthreads();
        float ss = 0.f;
        if (threadIdx.y == 0) {
            float4 b = part[c];
            a.x += b.x; a.y += b.y; a.z += b.z; a.w += b.w;
            ss = a.x*a.x + a.y*a.y + a.z*a.z + a.w*a.w;
        }
        #pragma unroll
        for (int o = 16; o; o >>= 1) ss += __shfl_xor_sync(0xffffffffu, ss, o);
        if (lane == 0) wss[warp] = ss;
        __syncthreads();
        if (threadIdx.y == 0) {
            float tot = wss[0] + wss[1] + wss[2] + wss[3] + wss[4];
            tot = fmaxf(tot, 1e-12f);
            float rs = rsqrtf(tot);
            rs = rs * (1.5f - 0.5f * tot * rs * rs);   // NR refine
            float4* o4 = reinterpret_cast<float4*>(g_xnorm);
            o4[(size_t)row * KD4 + c] = make_float4(a.x*rs, a.y*rs, a.z*rs, a.w*rs);
        }
    } else {
        const int p = blockIdx.x - BATCH;
        float4 v = make_float4(0.f, 0.f, 0.f, 0.f);
        float ss = 0.f;
        if (tid < 160) {
            v = pk[(size_t)p * KD4 + tid];
            ss = v.x*v.x + v.y*v.y + v.z*v.z + v.w*v.w;
        }
        #pragma unroll
        for (int o = 16; o; o >>= 1) ss += __shfl_xor_sync(0xffffffffu, ss, o);
        if (lane == 0) wss[warp] = ss;
        __syncthreads();
        float tot = wss[0] + wss[1] + wss[2] + wss[3] + wss[4];
        tot = fmaxf(tot, 1e-12f);
        float rs = rsqrtf(tot);
        rs = rs * (1.5f - 0.5f * tot * rs * rs);
        if (tid < 160) {
            float4* o4 = reinterpret_cast<float4*>(g_keynorm);
            o4[(size_t)p * KD4 + tid] = make_float4(v.x*rs, v.y*rs, v.z*rs, v.w*rs);
        }
    }
}

// ============================================================
// Kernel M2: blocks 0..127 -> sim GEMM (8 rows x 128 pools) + top-4
// (warps 0-7) overlapped with sim write (warps 8-15), then in-block
// gather with 12-deep load batching. Block 128 -> final reduce +
// usage (+ counter reset).
// ============================================================
__global__ __launch_bounds__(512)
void kM2(const float4* __restrict__ prompt, float* __restrict__ out) {
    const int bid = blockIdx.x;
    const int t   = threadIdx.x;
    const int w   = t >> 5, lane = t & 31;

    if (bid < POOL) {
        __shared__ float xs[8][644];
        __shared__ float sims[8][132];
        __shared__ float wsum[8];
        __shared__ int   sidx[32];

        const int rb = bid * 8;
        const int pg = t >> 4;             // 0..31 -> pools pg*4..+3
        const int ds = t & 15;             // dim slot

        // stage 8 x rows (coalesced)
        {
            const float4* xg = reinterpret_cast<const float4*>(g_xnorm);
            #pragma unroll
            for (int i = 0; i < 3; i++) {
                int l = t + 512 * i;                // covers 1280
                if (l < 1280) {
                    int r = l / 160, col = l - r * 160;
                    *reinterpret_cast<float4*>(&xs[r][col * 4]) =
                        xg[(size_t)(rb + r) * KD4 + col];
                }
            }
        }
        __syncthreads();

        const ulonglong2* kg = reinterpret_cast<const ulonglong2*>(g_keynorm);

        unsigned long long acc[4][8];      // [pool u][row r]
        #pragma unroll
        for (int u = 0; u < 4; u++)
            #pragma unroll
            for (int r = 0; r < 8; r++) acc[u][r] = 0ull;

        #pragma unroll
        for (int c = 0; c < 10; c++) {
            ulonglong2 kv[4];
            #pragma unroll
            for (int u = 0; u < 4; u++)
                kv[u] = kg[(size_t)(pg * 4 + u) * KD4 + c * 16 + ds];
            #pragma unroll
            for (int r = 0; r < 8; r++) {
                ulonglong2 xv = *reinterpret_cast<const ulonglong2*>(
                    &xs[r][c * 64 + ds * 4]);
                #pragma unroll
                for (int u = 0; u < 4; u++) {
                    fma2(acc[u][r], xv.x, kv[u].x);
                    fma2(acc[u][r], xv.y, kv[u].y);
                }
            }
        }

        #pragma unroll
        for (int u = 0; u < 4; u++) {
            #pragma unroll
            for (int r = 0; r < 8; r++) {
                float v = unpack_sum(acc[u][r]);
                #pragma unroll
                for (int o = 8; o; o >>= 1) v += __shfl_xor_sync(0xffffffffu, v, o);
                if (ds == 0) sims[r][pg * 4 + u] = v;
            }
        }
        __syncthreads();

        // ---- concurrent: warps 0-7 top-4 (rows 0-7); warps 8-15 write
        //      the 8x128 sim block to gmem (both only READ sims) ----
        if (w >= 8) {
            const int tt = t - 256;            // 0..255
            #pragma unroll
            for (int j = 0; j < 4; j++) {
                int l = tt + 256 * j;          // 0..1023
                int rr = l >> 7, pp = l & 127;
                out[OUT_SIM + (size_t)(rb + rr) * POOL + pp] = sims[rr][pp];
            }
        } else {
            // monotone-bits composite key, smallest index on ties
            // (matches jax.lax.top_k)
            float vals[4];
            #pragma unroll
            for (int s = 0; s < 4; s++) vals[s] = sims[w][lane + 32*s];
            float vsum = 0.f;
            #pragma unroll
            for (int k = 0; k < TOPK; k++) {
                unsigned long long best = 0ull;
                #pragma unroll
                for (int s = 0; s < 4; s++) {
                    unsigned u = __float_as_uint(vals[s]);
                    u = (u & 0x80000000u) ? ~u : (u | 0x80000000u);
                    unsigned long long comp =
                        ((unsigned long long)u << 32) | (127u - (lane + 32u*s));
                    if (comp > best) best = comp;
                }
                #pragma unroll
                for (int o = 16; o; o >>= 1) {
                    unsigned long long other = __shfl_xor_sync(0xffffffffu, best, o);
                    if (other > best) best = other;
                }
                unsigned pool = 127u - (unsigned)(best & 0xffffffffu);
                unsigned ub = (unsigned)(best >> 32);
                unsigned orig = (ub & 0x80000000u) ? (ub ^ 0x80000000u) : ~ub;
                vsum += __uint_as_float(orig);
                if (lane == (int)(pool & 31u)) vals[pool >> 5] = -1e30f;
                if (lane == 0) {
                    g_idx[(rb + w) * TOPK + k] = (int)pool;
                    sidx[w * 4 + k] = (int)pool;
                }
            }
            if (lane == 0) wsum[w] = vsum;
        }
        __syncthreads();

        if (t == 0) {
            float s = 0.f;
            #pragma unroll
            for (int j = 0; j < 8; j++) s += wsum[j];   // fixed order
            g_partial[bid] = s;
            __threadfence();             // publish g_idx/g_partial
            atomicAdd(&g_scnt, 1);
        }

        // ---- in-block gather: 32 segments x 576 float4 = 18432,
        //      36/thread, 12-deep batches (3 rounds) for deep MLP ----
        float4* outbp = reinterpret_cast<float4*>(out);
        const int obase = rb * 4 * PD4;
        #pragma unroll
        for (int s0 = 0; s0 < 36; s0 += 12) {
            float4 v[12]; int di[12];
            #pragma unroll
            for (int k = 0; k < 12; k++) {
                int i   = t + 512 * (s0 + k);
                int seg = i / PD4;
                int off = i - seg * PD4;
                v[k]  = prompt[(size_t)sidx[seg] * PD4 + off];
                di[k] = obase + i;
            }
            #pragma unroll
            for (int k = 0; k < 12; k++) outbp[di[k]] = v[k];
        }

    } else {
        // ---------------- final: reduce_sim + usage + reset ----------------
        __shared__ float red[128];
        __shared__ int   histo[128];
        if (t == 0) { waitge(&g_scnt, 128); __threadfence(); }
        __syncthreads();
        if (t < 128) { red[t] = g_partial[t]; histo[t] = 0; }
        __syncthreads();
        #pragma unroll
        for (int o = 64; o; o >>= 1) {
            if (t < o) red[t] += red[t + o];
            __syncthreads();
        }
        if (t == 0) out[OUT_RS] = red[0] * (1.0f / (float)BATCH);
        #pragma unroll
        for (int j = 0; j < 8; j++)
            atomicAdd(&histo[g_idx[t * 8 + j]], 1);
        __syncthreads();
        if (t < 128) out[OUT_US + t] = (float)histo[t];
        if (t == 0) g_scnt = 0;   // reset for next graph replay
    }
}

// ============================================================
extern "C" void kernel_launch(void* const* d_in, const int* in_sizes, int n_in,
                              void* d_out, int out_size) {
    const float* x      = (const float*)d_in[0];  // [1024, 100, 640]
    const float* prompt = (const float*)d_in[1];  // [128, 1, 2304]
    const float* pkey   = (const float*)d_in[2];  // [128, 640]
    float* out = (float*)d_out;

    k1_norm<<<BATCH + POOL, dim3(160, 2)>>>(
        reinterpret_cast<const float4*>(x),
        reinterpret_cast<const float4*>(pkey));
    kM2<<<POOL + 1, 512>>>(reinterpret_cast<const float4*>(prompt), out);
}